// round 2
// baseline (speedup 1.0000x reference)
#include <cuda_runtime.h>

#define DIN 128
#define H   32
#define MAX_NODES 100000
#define MAX_EDGES 3200000
#define CHUNK 256           // scan chunk
#define MAX_BLOCKS_SCAN 512 // >= ceil(MAX_NODES/CHUNK) = 391

// ---------------- scratch (no allocations allowed) ----------------
__device__ float g_Wf[DIN * H];          // fused weight  W_lin @ W_gc1
__device__ float g_bf[H];                // fused bias    b_lin @ W_gc1
__device__ int   g_deg_out[MAX_NODES];
__device__ int   g_deg_in[MAX_NODES];
__device__ int   g_off[MAX_NODES];       // CSR row offsets (excl. scan of deg_in)
__device__ int   g_cursor[MAX_NODES];    // scatter cursors
__device__ int   g_blocksum[MAX_BLOCKS_SCAN];
__device__ int   g_blockoff[MAX_BLOCKS_SCAN];
__device__ int   g_esrc[MAX_EDGES];      // src node id per edge, sorted by dst
__device__ float g_xw2[MAX_NODES * H];   // (x@Wf + bf) * rsqrt(max(deg_out,1))

// ---------------- kernel: zero degree counters ----------------
__global__ void k_zero(int n) {
    int i = blockIdx.x * blockDim.x + threadIdx.x;
    int stride = gridDim.x * blockDim.x;
    for (; i < n; i += stride) { g_deg_out[i] = 0; g_deg_in[i] = 0; }
}

// ---------------- kernel: fuse weights ----------------
__global__ void k_fuse(const float* __restrict__ Wlin, const float* __restrict__ blin,
                       const float* __restrict__ Wgc, int h1) {
    int idx = blockIdx.x * blockDim.x + threadIdx.x;
    if (idx < DIN * H) {
        int i = idx / H, j = idx % H;
        float s = 0.f;
        for (int k = 0; k < h1; k++) s += Wlin[i * h1 + k] * Wgc[k * H + j];
        g_Wf[idx] = s;
    }
    if (idx < H) {
        float s = 0.f;
        for (int k = 0; k < h1; k++) s += blin[k] * Wgc[k * H + idx];
        g_bf[idx] = s;
    }
}

// ---------------- kernel: degree histograms ----------------
__global__ void k_deg(const int* __restrict__ src, const int* __restrict__ dst, int E) {
    int i = blockIdx.x * blockDim.x + threadIdx.x;
    int stride = gridDim.x * blockDim.x;
    for (; i < E; i += stride) {
        atomicAdd(&g_deg_out[src[i]], 1);
        atomicAdd(&g_deg_in[dst[i]],  1);
    }
}

// ---------------- kernel: fused GEMM + out-degree norm ----------------
// One warp per node row; lane j owns output column j.
__global__ void k_gemm(const float* __restrict__ x, int n) {
    __shared__ float sW[DIN * H];
    __shared__ float sb[H];
    for (int t = threadIdx.x; t < DIN * H; t += blockDim.x) sW[t] = g_Wf[t];
    if (threadIdx.x < H) sb[threadIdx.x] = g_bf[threadIdx.x];
    __syncthreads();

    int warp   = (blockIdx.x * blockDim.x + threadIdx.x) >> 5;
    int lane   = threadIdx.x & 31;
    int nwarps = (gridDim.x * blockDim.x) >> 5;

    for (int row = warp; row < n; row += nwarps) {
        const float4* xr = reinterpret_cast<const float4*>(x + (size_t)row * DIN);
        float acc = sb[lane];
#pragma unroll
        for (int k4 = 0; k4 < DIN / 4; k4++) {
            float4 v = __ldg(&xr[k4]);
            acc += v.x * sW[(k4 * 4 + 0) * H + lane];
            acc += v.y * sW[(k4 * 4 + 1) * H + lane];
            acc += v.z * sW[(k4 * 4 + 2) * H + lane];
            acc += v.w * sW[(k4 * 4 + 3) * H + lane];
        }
        float d = (float)g_deg_out[row];
        if (d < 1.f) d = 1.f;
        g_xw2[row * H + lane] = acc * rsqrtf(d);
    }
}

// ---------------- scan pass 1: per-chunk sums ----------------
__global__ void k_scan1(int n, int nb) {
    __shared__ int s[CHUNK];
    int t = threadIdx.x;
    int i = blockIdx.x * CHUNK + t;
    s[t] = (i < n) ? g_deg_in[i] : 0;
    __syncthreads();
    // tree reduce
    for (int off = CHUNK / 2; off > 0; off >>= 1) {
        if (t < off) s[t] += s[t + off];
        __syncthreads();
    }
    if (t == 0) g_blocksum[blockIdx.x] = s[0];
}

// ---------------- scan pass 2: single-block exclusive scan of chunk sums ----------------
__global__ void k_scan2(int nb) {
    __shared__ int s[MAX_BLOCKS_SCAN];
    int t = threadIdx.x;  // blockDim = MAX_BLOCKS_SCAN
    int v = (t < nb) ? g_blocksum[t] : 0;
    s[t] = v;
    __syncthreads();
    for (int off = 1; off < MAX_BLOCKS_SCAN; off <<= 1) {
        int add = (t >= off) ? s[t - off] : 0;
        __syncthreads();
        s[t] += add;
        __syncthreads();
    }
    if (t < nb) g_blockoff[t] = s[t] - v;  // exclusive
}

// ---------------- scan pass 3: per-chunk exclusive scan + base offset ----------------
__global__ void k_scan3(int n) {
    __shared__ int s[CHUNK];
    int t = threadIdx.x;
    int i = blockIdx.x * CHUNK + t;
    int v = (i < n) ? g_deg_in[i] : 0;
    s[t] = v;
    __syncthreads();
    for (int off = 1; off < CHUNK; off <<= 1) {
        int add = (t >= off) ? s[t - off] : 0;
        __syncthreads();
        s[t] += add;
        __syncthreads();
    }
    if (i < n) {
        int off = g_blockoff[blockIdx.x] + s[t] - v;  // exclusive
        g_off[i]    = off;
        g_cursor[i] = off;
    }
}

// ---------------- kernel: counting-sort scatter (src ids into dst buckets) ----------------
__global__ void k_scatter(const int* __restrict__ src, const int* __restrict__ dst, int E) {
    int i = blockIdx.x * blockDim.x + threadIdx.x;
    int stride = gridDim.x * blockDim.x;
    for (; i < E; i += stride) {
        int d = dst[i];
        int p = atomicAdd(&g_cursor[d], 1);
        g_esrc[p] = src[i];
    }
}

// ---------------- kernel: gather-aggregate (the hot one, no float atomics) ----------------
// One warp per dst node; lane j owns feature j; unroll x4 for gather MLP.
__global__ void k_agg(float* __restrict__ out, const float* __restrict__ bgc, int n) {
    int warp   = (blockIdx.x * blockDim.x + threadIdx.x) >> 5;
    int lane   = threadIdx.x & 31;
    int nwarps = (gridDim.x * blockDim.x) >> 5;

    for (int row = warp; row < n; row += nwarps) {
        int start = g_off[row];
        int deg   = g_deg_in[row];
        int end   = start + deg;
        float acc = 0.f;
        int i = start;
        for (; i + 4 <= end; i += 4) {
            int s0 = __ldg(&g_esrc[i + 0]);
            int s1 = __ldg(&g_esrc[i + 1]);
            int s2 = __ldg(&g_esrc[i + 2]);
            int s3 = __ldg(&g_esrc[i + 3]);
            float v0 = __ldg(&g_xw2[s0 * H + lane]);
            float v1 = __ldg(&g_xw2[s1 * H + lane]);
            float v2 = __ldg(&g_xw2[s2 * H + lane]);
            float v3 = __ldg(&g_xw2[s3 * H + lane]);
            acc += v0 + v1 + v2 + v3;
        }
        for (; i < end; i++)
            acc += __ldg(&g_xw2[__ldg(&g_esrc[i]) * H + lane]);

        float d = (float)(deg > 0 ? deg : 1);
        out[row * H + lane] = acc * rsqrtf(d) + __ldg(&bgc[lane]);
    }
}

// ---------------- launch ----------------
extern "C" void kernel_launch(void* const* d_in, const int* in_sizes, int n_in,
                              void* d_out, int out_size) {
    const float* x    = (const float*)d_in[0];
    const int*   src  = (const int*)  d_in[1];
    const int*   dst  = (const int*)  d_in[2];
    const float* Wlin = (const float*)d_in[3];
    const float* blin = (const float*)d_in[4];
    const float* Wgc  = (const float*)d_in[5];
    const float* bgc  = (const float*)d_in[6];
    float* out = (float*)d_out;

    int n  = in_sizes[0] / DIN;   // 100000
    int E  = in_sizes[1];         // 3200000
    int h1 = in_sizes[4];         // 32
    int nb = (n + CHUNK - 1) / CHUNK;  // 391

    k_zero<<<256, 256>>>(n);
    k_fuse<<<(DIN * H + 255) / 256, 256>>>(Wlin, blin, Wgc, h1);
    k_deg<<<1024, 256>>>(src, dst, E);

    k_gemm<<<1184, 256>>>(x, n);                 // needs deg_out

    k_scan1<<<nb, CHUNK>>>(n, nb);
    k_scan2<<<1, MAX_BLOCKS_SCAN>>>(nb);
    k_scan3<<<nb, CHUNK>>>(n);

    k_scatter<<<2048, 256>>>(src, dst, E);
    k_agg<<<1184, 256>>>(out, bgc, n);           // writes every output element
}

// round 4
// speedup vs baseline: 1.1889x; 1.1889x over previous
#include <cuda_runtime.h>

#define DIN 128
#define H   32
#define MAX_NODES 100000
#define MAX_EDGES 3200000
#define CHUNK 256
#define MAX_BLOCKS_SCAN 512
#define RROWS 8   // rows per warp in GEMM

// ---------------- scratch ----------------
__device__ float g_Wf[DIN * H];
__device__ float g_bf[H];
__device__ int   g_deg_out[MAX_NODES];
__device__ int   g_deg_in[MAX_NODES];
__device__ int   g_off[MAX_NODES];
__device__ int   g_cursor[MAX_NODES];
__device__ int   g_blocksum[MAX_BLOCKS_SCAN];
__device__ int   g_blockoff[MAX_BLOCKS_SCAN];
__device__ int   g_esrc[MAX_EDGES];
__device__ float g_xw2[MAX_NODES * H];

// ---------------- zero degree counters ----------------
__global__ void k_zero(int n) {
    int i = blockIdx.x * blockDim.x + threadIdx.x;
    int stride = gridDim.x * blockDim.x;
    for (; i < n; i += stride) { g_deg_out[i] = 0; g_deg_in[i] = 0; }
}

// ---------------- fuse weights: Wf = W_lin @ W_gc1, bf = b_lin @ W_gc1 ----------------
__global__ void k_fuse(const float* __restrict__ Wlin, const float* __restrict__ blin,
                       const float* __restrict__ Wgc, int h1) {
    int idx = blockIdx.x * blockDim.x + threadIdx.x;
    if (idx < DIN * H) {
        int i = idx / H, j = idx % H;
        float s = 0.f;
        for (int k = 0; k < h1; k++) s += Wlin[i * h1 + k] * Wgc[k * H + j];
        g_Wf[idx] = s;
    }
    if (idx < H) {
        float s = 0.f;
        for (int k = 0; k < h1; k++) s += blin[k] * Wgc[k * H + idx];
        g_bf[idx] = s;
    }
}

// ---------------- degree histograms (int2 index loads) ----------------
__global__ void __launch_bounds__(256) k_deg(const int* __restrict__ src,
                                             const int* __restrict__ dst, int E) {
    int i = blockIdx.x * blockDim.x + threadIdx.x;
    int stride = gridDim.x * blockDim.x;
    int E2 = E >> 1;
    const int2* s2 = reinterpret_cast<const int2*>(src);
    const int2* d2 = reinterpret_cast<const int2*>(dst);
    for (int j = i; j < E2; j += stride) {
        int2 s = __ldg(&s2[j]);
        int2 d = __ldg(&d2[j]);
        atomicAdd(&g_deg_out[s.x], 1);
        atomicAdd(&g_deg_out[s.y], 1);
        atomicAdd(&g_deg_in[d.x],  1);
        atomicAdd(&g_deg_in[d.y],  1);
    }
    if (i == 0 && (E & 1)) {
        atomicAdd(&g_deg_out[src[E - 1]], 1);
        atomicAdd(&g_deg_in[dst[E - 1]],  1);
    }
}

// ---------------- fused GEMM + out-degree norm; 8 rows/warp register blocking ----------------
__global__ void __launch_bounds__(256) k_gemm(const float* __restrict__ x, int n) {
    __shared__ float sW[DIN * H];
    __shared__ float sb[H];
    for (int t = threadIdx.x; t < DIN * H; t += blockDim.x) sW[t] = g_Wf[t];
    if (threadIdx.x < H) sb[threadIdx.x] = g_bf[threadIdx.x];
    __syncthreads();

    int warp    = (blockIdx.x * blockDim.x + threadIdx.x) >> 5;
    int lane    = threadIdx.x & 31;
    int nwarps  = (gridDim.x * blockDim.x) >> 5;
    int ngroups = n / RROWS;
    float bias  = sb[lane];

    for (int g = warp; g < ngroups; g += nwarps) {
        int row0 = g * RROWS;
        const float4* xr = reinterpret_cast<const float4*>(x + (size_t)row0 * DIN);
        float acc[RROWS];
#pragma unroll
        for (int r = 0; r < RROWS; r++) acc[r] = 0.f;

#pragma unroll 4
        for (int k4 = 0; k4 < DIN / 4; k4++) {
            float w0 = sW[(k4 * 4 + 0) * H + lane];
            float w1 = sW[(k4 * 4 + 1) * H + lane];
            float w2 = sW[(k4 * 4 + 2) * H + lane];
            float w3 = sW[(k4 * 4 + 3) * H + lane];
#pragma unroll
            for (int r = 0; r < RROWS; r++) {
                float4 v = __ldg(&xr[r * (DIN / 4) + k4]);  // uniform -> broadcast
                acc[r] += v.x * w0 + v.y * w1 + v.z * w2 + v.w * w3;
            }
        }
#pragma unroll
        for (int r = 0; r < RROWS; r++) {
            int row = row0 + r;
            float d = (float)__ldg(&g_deg_out[row]);
            if (d < 1.f) d = 1.f;
            g_xw2[row * H + lane] = (acc[r] + bias) * rsqrtf(d);
        }
    }

    // tail rows (n % RROWS)
    if (warp == 0) {
        for (int row = ngroups * RROWS; row < n; row++) {
            const float4* xr = reinterpret_cast<const float4*>(x + (size_t)row * DIN);
            float acc = bias;
            for (int k4 = 0; k4 < DIN / 4; k4++) {
                float4 v = __ldg(&xr[k4]);
                acc += v.x * sW[(k4 * 4 + 0) * H + lane] + v.y * sW[(k4 * 4 + 1) * H + lane]
                     + v.z * sW[(k4 * 4 + 2) * H + lane] + v.w * sW[(k4 * 4 + 3) * H + lane];
            }
            float d = (float)__ldg(&g_deg_out[row]);
            if (d < 1.f) d = 1.f;
            g_xw2[row * H + lane] = acc * rsqrtf(d);
        }
    }
}

// ---------------- scan pass 1: per-chunk sums ----------------
__global__ void k_scan1(int n, int nb) {
    __shared__ int s[CHUNK];
    int t = threadIdx.x;
    int i = blockIdx.x * CHUNK + t;
    s[t] = (i < n) ? g_deg_in[i] : 0;
    __syncthreads();
    for (int off = CHUNK / 2; off > 0; off >>= 1) {
        if (t < off) s[t] += s[t + off];
        __syncthreads();
    }
    if (t == 0) g_blocksum[blockIdx.x] = s[0];
}

// ---------------- scan pass 2 ----------------
__global__ void k_scan2(int nb) {
    __shared__ int s[MAX_BLOCKS_SCAN];
    int t = threadIdx.x;
    int v = (t < nb) ? g_blocksum[t] : 0;
    s[t] = v;
    __syncthreads();
    for (int off = 1; off < MAX_BLOCKS_SCAN; off <<= 1) {
        int add = (t >= off) ? s[t - off] : 0;
        __syncthreads();
        s[t] += add;
        __syncthreads();
    }
    if (t < nb) g_blockoff[t] = s[t] - v;
}

// ---------------- scan pass 3 ----------------
__global__ void k_scan3(int n) {
    __shared__ int s[CHUNK];
    int t = threadIdx.x;
    int i = blockIdx.x * CHUNK + t;
    int v = (i < n) ? g_deg_in[i] : 0;
    s[t] = v;
    __syncthreads();
    for (int off = 1; off < CHUNK; off <<= 1) {
        int add = (t >= off) ? s[t - off] : 0;
        __syncthreads();
        s[t] += add;
        __syncthreads();
    }
    if (i < n) {
        int off = g_blockoff[blockIdx.x] + s[t] - v;
        g_off[i]    = off;
        g_cursor[i] = off;
    }
}

// ---------------- counting-sort scatter ----------------
__global__ void __launch_bounds__(256) k_scatter(const int* __restrict__ src,
                                                 const int* __restrict__ dst, int E) {
    int i = blockIdx.x * blockDim.x + threadIdx.x;
    int stride = gridDim.x * blockDim.x;
    for (; i < E; i += stride) {
        int d = dst[i];
        int p = atomicAdd(&g_cursor[d], 1);
        g_esrc[p] = src[i];
    }
}

// ---------------- gather-aggregate; warp per node; MLP=8 ----------------
__global__ void __launch_bounds__(256) k_agg(float* __restrict__ out,
                                             const float* __restrict__ bgc, int n) {
    int warp   = (blockIdx.x * blockDim.x + threadIdx.x) >> 5;
    int lane   = threadIdx.x & 31;
    int nwarps = (gridDim.x * blockDim.x) >> 5;
    float bias = __ldg(&bgc[lane]);

    for (int row = warp; row < n; row += nwarps) {
        int start = g_off[row];
        int deg   = g_deg_in[row];
        int end   = start + deg;
        float acc = 0.f;
        int i = start;
        for (; i + 8 <= end; i += 8) {
            int s0 = __ldg(&g_esrc[i + 0]);
            int s1 = __ldg(&g_esrc[i + 1]);
            int s2 = __ldg(&g_esrc[i + 2]);
            int s3 = __ldg(&g_esrc[i + 3]);
            int s4 = __ldg(&g_esrc[i + 4]);
            int s5 = __ldg(&g_esrc[i + 5]);
            int s6 = __ldg(&g_esrc[i + 6]);
            int s7 = __ldg(&g_esrc[i + 7]);
            float v0 = __ldg(&g_xw2[s0 * H + lane]);
            float v1 = __ldg(&g_xw2[s1 * H + lane]);
            float v2 = __ldg(&g_xw2[s2 * H + lane]);
            float v3 = __ldg(&g_xw2[s3 * H + lane]);
            float v4 = __ldg(&g_xw2[s4 * H + lane]);
            float v5 = __ldg(&g_xw2[s5 * H + lane]);
            float v6 = __ldg(&g_xw2[s6 * H + lane]);
            float v7 = __ldg(&g_xw2[s7 * H + lane]);
            acc += ((v0 + v1) + (v2 + v3)) + ((v4 + v5) + (v6 + v7));
        }
        for (; i < end; i++)
            acc += __ldg(&g_xw2[__ldg(&g_esrc[i]) * H + lane]);

        float d = (float)(deg > 0 ? deg : 1);
        out[row * H + lane] = acc * rsqrtf(d) + bias;
    }
}

// ---------------- launch ----------------
extern "C" void kernel_launch(void* const* d_in, const int* in_sizes, int n_in,
                              void* d_out, int out_size) {
    const float* x    = (const float*)d_in[0];
    const int*   src  = (const int*)  d_in[1];
    const int*   dst  = (const int*)  d_in[2];
    const float* Wlin = (const float*)d_in[3];
    const float* blin = (const float*)d_in[4];
    const float* Wgc  = (const float*)d_in[5];
    const float* bgc  = (const float*)d_in[6];
    float* out = (float*)d_out;

    int n  = in_sizes[0] / DIN;
    int E  = in_sizes[1];
    int h1 = in_sizes[4];
    int nb = (n + CHUNK - 1) / CHUNK;

    k_zero<<<256, 256>>>(n);
    k_fuse<<<(DIN * H + 255) / 256, 256>>>(Wlin, blin, Wgc, h1);
    k_deg<<<1024, 256>>>(src, dst, E);

    k_gemm<<<1184, 256>>>(x, n);

    k_scan1<<<nb, CHUNK>>>(n, nb);
    k_scan2<<<1, MAX_BLOCKS_SCAN>>>(nb);
    k_scan3<<<nb, CHUNK>>>(n);

    k_scatter<<<2048, 256>>>(src, dst, E);
    k_agg<<<1184, 256>>>(out, bgc, n);
}

// round 5
// speedup vs baseline: 1.2000x; 1.0094x over previous
#include <cuda_runtime.h>

#define DIN 128
#define H   32
#define MAX_NODES 100000
#define MAX_EDGES 3200000
#define CHUNK 256
#define MAX_BLOCKS_SCAN 512
#define TILE_R 128   // rows per block in GEMM
#define WR 16        // rows per warp in GEMM

// ---------------- scratch ----------------
__device__ float g_Wf[DIN * H];
__device__ float g_bf[H];
__device__ int   g_deg_out[MAX_NODES];
__device__ int   g_deg_in[MAX_NODES];
__device__ int   g_off[MAX_NODES];
__device__ int   g_cursor[MAX_NODES];
__device__ int   g_blocksum[MAX_BLOCKS_SCAN];
__device__ int   g_blockoff[MAX_BLOCKS_SCAN];
__device__ int   g_esrc[MAX_EDGES];
__device__ float g_xw2[MAX_NODES * H];

// ---------------- init: zero degree counters + fuse weights ----------------
__global__ void k_init(const float* __restrict__ Wlin, const float* __restrict__ blin,
                       const float* __restrict__ Wgc, int h1, int n) {
    int idx = blockIdx.x * blockDim.x + threadIdx.x;
    int stride = gridDim.x * blockDim.x;
    for (int i = idx; i < n; i += stride) { g_deg_out[i] = 0; g_deg_in[i] = 0; }

    if (idx < DIN * H) {
        int i = idx / H, j = idx % H;
        float s = 0.f;
        for (int k = 0; k < h1; k++) s += Wlin[i * h1 + k] * Wgc[k * H + j];
        g_Wf[idx] = s;
    }
    if (idx < H) {
        float s = 0.f;
        for (int k = 0; k < h1; k++) s += blin[k] * Wgc[k * H + idx];
        g_bf[idx] = s;
    }
}

// ---------------- degree histograms (int2 index loads) ----------------
__global__ void __launch_bounds__(256) k_deg(const int* __restrict__ src,
                                             const int* __restrict__ dst, int E) {
    int i = blockIdx.x * blockDim.x + threadIdx.x;
    int stride = gridDim.x * blockDim.x;
    int E2 = E >> 1;
    const int2* s2 = reinterpret_cast<const int2*>(src);
    const int2* d2 = reinterpret_cast<const int2*>(dst);
    for (int j = i; j < E2; j += stride) {
        int2 s = __ldg(&s2[j]);
        int2 d = __ldg(&d2[j]);
        atomicAdd(&g_deg_out[s.x], 1);
        atomicAdd(&g_deg_out[s.y], 1);
        atomicAdd(&g_deg_in[d.x],  1);
        atomicAdd(&g_deg_in[d.y],  1);
    }
    if (i == 0 && (E & 1)) {
        atomicAdd(&g_deg_out[src[E - 1]], 1);
        atomicAdd(&g_deg_in[dst[E - 1]],  1);
    }
}

// ---------------- fused GEMM + out-degree norm ----------------
// Block stages a 128x128 x-tile into smem (coalesced LDG.128), then each warp
// register-blocks 16 rows; x read via broadcast LDS.128. FFMA-pipe bound.
__global__ void __launch_bounds__(256) k_gemm(const float* __restrict__ x, int n) {
    extern __shared__ float smem[];
    float* sX = smem;                      // TILE_R*DIN floats (64KB)
    float* sW = smem + TILE_R * DIN;       // DIN*H floats (16KB)

    int tid = threadIdx.x;
    for (int t = tid; t < DIN * H; t += 256) sW[t] = g_Wf[t];

    int row0 = blockIdx.x * TILE_R;
    float4* sX4 = reinterpret_cast<float4*>(sX);
    const float4* xg = reinterpret_cast<const float4*>(x);
    int base4 = row0 * (DIN / 4);
    for (int i = tid; i < TILE_R * (DIN / 4); i += 256) {
        int row = row0 + (i >> 5);  // DIN/4 == 32
        sX4[i] = (row < n) ? __ldg(&xg[base4 + i]) : make_float4(0.f, 0.f, 0.f, 0.f);
    }
    __syncthreads();

    int w = tid >> 5, lane = tid & 31;
    float bias = g_bf[lane];
    int r0 = w * WR;

    float acc[WR];
#pragma unroll
    for (int r = 0; r < WR; r++) acc[r] = 0.f;

#pragma unroll 2
    for (int k4 = 0; k4 < DIN / 4; k4++) {
        float w0 = sW[(k4 * 4 + 0) * H + lane];
        float w1 = sW[(k4 * 4 + 1) * H + lane];
        float w2 = sW[(k4 * 4 + 2) * H + lane];
        float w3 = sW[(k4 * 4 + 3) * H + lane];
#pragma unroll
        for (int r = 0; r < WR; r++) {
            float4 v = sX4[(r0 + r) * (DIN / 4) + k4];  // broadcast LDS.128
            acc[r] += v.x * w0 + v.y * w1 + v.z * w2 + v.w * w3;
        }
    }

#pragma unroll
    for (int r = 0; r < WR; r++) {
        int row = row0 + r0 + r;
        if (row < n) {
            float d = (float)g_deg_out[row];
            if (d < 1.f) d = 1.f;
            g_xw2[row * H + lane] = (acc[r] + bias) * rsqrtf(d);
        }
    }
}

// ---------------- scan pass 1: per-chunk sums ----------------
__global__ void k_scan1(int n, int nb) {
    __shared__ int s[CHUNK];
    int t = threadIdx.x;
    int i = blockIdx.x * CHUNK + t;
    s[t] = (i < n) ? g_deg_in[i] : 0;
    __syncthreads();
    for (int off = CHUNK / 2; off > 0; off >>= 1) {
        if (t < off) s[t] += s[t + off];
        __syncthreads();
    }
    if (t == 0) g_blocksum[blockIdx.x] = s[0];
}

// ---------------- scan pass 2 ----------------
__global__ void k_scan2(int nb) {
    __shared__ int s[MAX_BLOCKS_SCAN];
    int t = threadIdx.x;
    int v = (t < nb) ? g_blocksum[t] : 0;
    s[t] = v;
    __syncthreads();
    for (int off = 1; off < MAX_BLOCKS_SCAN; off <<= 1) {
        int add = (t >= off) ? s[t - off] : 0;
        __syncthreads();
        s[t] += add;
        __syncthreads();
    }
    if (t < nb) g_blockoff[t] = s[t] - v;
}

// ---------------- scan pass 3 ----------------
__global__ void k_scan3(int n) {
    __shared__ int s[CHUNK];
    int t = threadIdx.x;
    int i = blockIdx.x * CHUNK + t;
    int v = (i < n) ? g_deg_in[i] : 0;
    s[t] = v;
    __syncthreads();
    for (int off = 1; off < CHUNK; off <<= 1) {
        int add = (t >= off) ? s[t - off] : 0;
        __syncthreads();
        s[t] += add;
        __syncthreads();
    }
    if (i < n) {
        int off = g_blockoff[blockIdx.x] + s[t] - v;
        g_off[i]    = off;
        g_cursor[i] = off;
    }
}

// ---------------- counting-sort scatter ----------------
__global__ void __launch_bounds__(256) k_scatter(const int* __restrict__ src,
                                                 const int* __restrict__ dst, int E) {
    int i = blockIdx.x * blockDim.x + threadIdx.x;
    int stride = gridDim.x * blockDim.x;
    for (; i < E; i += stride) {
        int d = dst[i];
        int p = atomicAdd(&g_cursor[d], 1);
        g_esrc[p] = src[i];
    }
}

// ---------------- gather-aggregate; warp per node; MLP=8 ----------------
__global__ void __launch_bounds__(256) k_agg(float* __restrict__ out,
                                             const float* __restrict__ bgc, int n) {
    int warp   = (blockIdx.x * blockDim.x + threadIdx.x) >> 5;
    int lane   = threadIdx.x & 31;
    int nwarps = (gridDim.x * blockDim.x) >> 5;
    float bias = __ldg(&bgc[lane]);

    for (int row = warp; row < n; row += nwarps) {
        int start = g_off[row];
        int deg   = g_deg_in[row];
        int end   = start + deg;
        float acc = 0.f;
        int i = start;
        for (; i + 8 <= end; i += 8) {
            int s0 = __ldg(&g_esrc[i + 0]);
            int s1 = __ldg(&g_esrc[i + 1]);
            int s2 = __ldg(&g_esrc[i + 2]);
            int s3 = __ldg(&g_esrc[i + 3]);
            int s4 = __ldg(&g_esrc[i + 4]);
            int s5 = __ldg(&g_esrc[i + 5]);
            int s6 = __ldg(&g_esrc[i + 6]);
            int s7 = __ldg(&g_esrc[i + 7]);
            float v0 = __ldg(&g_xw2[s0 * H + lane]);
            float v1 = __ldg(&g_xw2[s1 * H + lane]);
            float v2 = __ldg(&g_xw2[s2 * H + lane]);
            float v3 = __ldg(&g_xw2[s3 * H + lane]);
            float v4 = __ldg(&g_xw2[s4 * H + lane]);
            float v5 = __ldg(&g_xw2[s5 * H + lane]);
            float v6 = __ldg(&g_xw2[s6 * H + lane]);
            float v7 = __ldg(&g_xw2[s7 * H + lane]);
            acc += ((v0 + v1) + (v2 + v3)) + ((v4 + v5) + (v6 + v7));
        }
        for (; i < end; i++)
            acc += __ldg(&g_xw2[__ldg(&g_esrc[i]) * H + lane]);

        float d = (float)(deg > 0 ? deg : 1);
        out[row * H + lane] = acc * rsqrtf(d) + bias;
    }
}

// ---------------- launch ----------------
extern "C" void kernel_launch(void* const* d_in, const int* in_sizes, int n_in,
                              void* d_out, int out_size) {
    const float* x    = (const float*)d_in[0];
    const int*   src  = (const int*)  d_in[1];
    const int*   dst  = (const int*)  d_in[2];
    const float* Wlin = (const float*)d_in[3];
    const float* blin = (const float*)d_in[4];
    const float* Wgc  = (const float*)d_in[5];
    const float* bgc  = (const float*)d_in[6];
    float* out = (float*)d_out;

    int n  = in_sizes[0] / DIN;
    int E  = in_sizes[1];
    int h1 = in_sizes[4];
    int nb = (n + CHUNK - 1) / CHUNK;

    k_init<<<256, 256>>>(Wlin, blin, Wgc, h1, n);
    k_deg<<<1024, 256>>>(src, dst, E);

    static const size_t smemsz = (size_t)(TILE_R * DIN + DIN * H) * sizeof(float);  // 81920
    cudaFuncSetAttribute(k_gemm, cudaFuncAttributeMaxDynamicSharedMemorySize, (int)smemsz);
    int gblk = (n + TILE_R - 1) / TILE_R;
    k_gemm<<<gblk, 256, smemsz>>>(x, n);

    k_scan1<<<nb, CHUNK>>>(n, nb);
    k_scan2<<<1, MAX_BLOCKS_SCAN>>>(nb);
    k_scan3<<<nb, CHUNK>>>(n);

    k_scatter<<<2048, 256>>>(src, dst, E);
    k_agg<<<1184, 256>>>(out, bgc, n);
}

// round 6
// speedup vs baseline: 1.2475x; 1.0396x over previous
#include <cuda_runtime.h>
#include <cuda_fp16.h>

#define DIN 128
#define H   32
#define MAX_NODES 100000
#define MAX_EDGES 3200000
#define CHUNK 256
#define MAX_BLOCKS_SCAN 512
#define TILE_R 128
#define WR 16

// ---------------- scratch ----------------
__device__ float   g_Wf[DIN * H];
__device__ float   g_bf[H];
__device__ int     g_deg_out[MAX_NODES];
__device__ int     g_deg_in[MAX_NODES];
__device__ int     g_off[MAX_NODES];
__device__ int     g_cursor[MAX_NODES];
__device__ int     g_blocksum[MAX_BLOCKS_SCAN];
__device__ int     g_blockoff[MAX_BLOCKS_SCAN];
__device__ int     g_esrc[MAX_EDGES];
__device__ __half2 g_xw2h[MAX_NODES * (H / 2)];  // fp16 packed features, 64B/row

// ---------------- init: zero degrees + fuse weights ----------------
__global__ void k_init(const float* __restrict__ Wlin, const float* __restrict__ blin,
                       const float* __restrict__ Wgc, int h1, int n) {
    int idx = blockIdx.x * blockDim.x + threadIdx.x;
    int stride = gridDim.x * blockDim.x;
    for (int i = idx; i < n; i += stride) { g_deg_out[i] = 0; g_deg_in[i] = 0; }

    if (idx < DIN * H) {
        int i = idx / H, j = idx % H;
        float s = 0.f;
        for (int k = 0; k < h1; k++) s += Wlin[i * h1 + k] * Wgc[k * H + j];
        g_Wf[idx] = s;
    }
    if (idx < H) {
        float s = 0.f;
        for (int k = 0; k < h1; k++) s += blin[k] * Wgc[k * H + idx];
        g_bf[idx] = s;
    }
}

// ---------------- degree histograms ----------------
__global__ void __launch_bounds__(256) k_deg(const int* __restrict__ src,
                                             const int* __restrict__ dst, int E) {
    int i = blockIdx.x * blockDim.x + threadIdx.x;
    int stride = gridDim.x * blockDim.x;
    int E2 = E >> 1;
    const int2* s2 = reinterpret_cast<const int2*>(src);
    const int2* d2 = reinterpret_cast<const int2*>(dst);
    for (int j = i; j < E2; j += stride) {
        int2 s = __ldg(&s2[j]);
        int2 d = __ldg(&d2[j]);
        atomicAdd(&g_deg_out[s.x], 1);
        atomicAdd(&g_deg_out[s.y], 1);
        atomicAdd(&g_deg_in[d.x],  1);
        atomicAdd(&g_deg_in[d.y],  1);
    }
    if (i == 0 && (E & 1)) {
        atomicAdd(&g_deg_out[src[E - 1]], 1);
        atomicAdd(&g_deg_in[dst[E - 1]],  1);
    }
}

// ---------------- scan pass 1: per-chunk sums (shuffle reduce) ----------------
__global__ void k_scan1(int n, int nb) {
    __shared__ int ws[8];
    int t = threadIdx.x;
    int i = blockIdx.x * CHUNK + t;
    int v = (i < n) ? g_deg_in[i] : 0;
#pragma unroll
    for (int o = 16; o > 0; o >>= 1) v += __shfl_xor_sync(0xffffffffu, v, o);
    if ((t & 31) == 0) ws[t >> 5] = v;
    __syncthreads();
    if (t < 8) {
        int s = ws[t];
#pragma unroll
        for (int o = 4; o > 0; o >>= 1) s += __shfl_xor_sync(0xffu, s, o);
        if (t == 0) g_blocksum[blockIdx.x] = s;
    }
}

// ---------------- fused GEMM + out-degree norm (smem-staged, fp16 output) ----------------
__global__ void __launch_bounds__(256) k_gemm(const float* __restrict__ x, int n) {
    extern __shared__ float smem[];
    float* sX = smem;                 // TILE_R*DIN (64KB)
    float* sW = smem + TILE_R * DIN;  // DIN*H (16KB)

    int tid = threadIdx.x;
    for (int t = tid; t < DIN * H; t += 256) sW[t] = g_Wf[t];

    int row0 = blockIdx.x * TILE_R;
    float4* sX4 = reinterpret_cast<float4*>(sX);
    const float4* xg = reinterpret_cast<const float4*>(x);
    int base4 = row0 * (DIN / 4);
    for (int i = tid; i < TILE_R * (DIN / 4); i += 256) {
        int row = row0 + (i >> 5);
        sX4[i] = (row < n) ? __ldg(&xg[base4 + i]) : make_float4(0.f, 0.f, 0.f, 0.f);
    }
    __syncthreads();

    int w = tid >> 5, lane = tid & 31;
    float bias = g_bf[lane];
    int r0 = w * WR;

    float acc[WR];
#pragma unroll
    for (int r = 0; r < WR; r++) acc[r] = 0.f;

#pragma unroll 2
    for (int k4 = 0; k4 < DIN / 4; k4++) {
        float w0 = sW[(k4 * 4 + 0) * H + lane];
        float w1 = sW[(k4 * 4 + 1) * H + lane];
        float w2 = sW[(k4 * 4 + 2) * H + lane];
        float w3 = sW[(k4 * 4 + 3) * H + lane];
#pragma unroll
        for (int r = 0; r < WR; r++) {
            float4 v = sX4[(r0 + r) * (DIN / 4) + k4];
            acc[r] += v.x * w0 + v.y * w1 + v.z * w2 + v.w * w3;
        }
    }

#pragma unroll
    for (int r = 0; r < WR; r++) {
        int row = row0 + r0 + r;
        if (row < n) {
            float d = (float)g_deg_out[row];
            if (d < 1.f) d = 1.f;
            float val = (acc[r] + bias) * rsqrtf(d);
            float vo = __shfl_down_sync(0xffffffffu, val, 1);
            if ((lane & 1) == 0)
                g_xw2h[row * (H / 2) + (lane >> 1)] = __floats2half2_rn(val, vo);
        }
    }
}

// ---------------- scan pass 2 ----------------
__global__ void k_scan2(int nb) {
    __shared__ int s[MAX_BLOCKS_SCAN];
    int t = threadIdx.x;
    int v = (t < nb) ? g_blocksum[t] : 0;
    s[t] = v;
    __syncthreads();
    for (int off = 1; off < MAX_BLOCKS_SCAN; off <<= 1) {
        int add = (t >= off) ? s[t - off] : 0;
        __syncthreads();
        s[t] += add;
        __syncthreads();
    }
    if (t < nb) g_blockoff[t] = s[t] - v;
}

// ---------------- scan pass 3 ----------------
__global__ void k_scan3(int n) {
    __shared__ int s[CHUNK];
    int t = threadIdx.x;
    int i = blockIdx.x * CHUNK + t;
    int v = (i < n) ? g_deg_in[i] : 0;
    s[t] = v;
    __syncthreads();
    for (int off = 1; off < CHUNK; off <<= 1) {
        int add = (t >= off) ? s[t - off] : 0;
        __syncthreads();
        s[t] += add;
        __syncthreads();
    }
    if (i < n) {
        int off = g_blockoff[blockIdx.x] + s[t] - v;
        g_off[i]    = off;
        g_cursor[i] = off;
    }
}

// ---------------- counting-sort scatter ----------------
__global__ void __launch_bounds__(256) k_scatter(const int* __restrict__ src,
                                                 const int* __restrict__ dst, int E) {
    int i = blockIdx.x * blockDim.x + threadIdx.x;
    int stride = gridDim.x * blockDim.x;
    for (; i < E; i += stride) {
        int d = dst[i];
        int p = atomicAdd(&g_cursor[d], 1);
        g_esrc[p] = src[i];
    }
}

// ---------------- gather-aggregate: warp = 2 edges/iter, fp16 rows ----------------
// Half-warp per edge: sub = lane>>4 selects edge, fl = lane&15 selects feature pair.
__global__ void __launch_bounds__(256) k_agg(float* __restrict__ out,
                                             const float* __restrict__ bgc, int n) {
    int warp   = (blockIdx.x * blockDim.x + threadIdx.x) >> 5;
    int lane   = threadIdx.x & 31;
    int nwarps = (gridDim.x * blockDim.x) >> 5;
    int sub    = lane >> 4;   // which edge of the pair
    int fl     = lane & 15;   // feature-pair index
    float bx = __ldg(&bgc[2 * fl]);
    float by = __ldg(&bgc[2 * fl + 1]);

    for (int row = warp; row < n; row += nwarps) {
        int start = g_off[row];
        int deg   = g_deg_in[row];
        int end   = start + deg;
        float ax = 0.f, ay = 0.f;
        int i = start;
        // 8 edges per iteration (4 per half-warp) for MLP
        for (; i + 8 <= end; i += 8) {
            int s0 = __ldg(&g_esrc[i + 0 + sub * 4]);
            int s1 = __ldg(&g_esrc[i + 1 + sub * 4]);
            int s2 = __ldg(&g_esrc[i + 2 + sub * 4]);
            int s3 = __ldg(&g_esrc[i + 3 + sub * 4]);
            float2 f0 = __half22float2(g_xw2h[s0 * (H / 2) + fl]);
            float2 f1 = __half22float2(g_xw2h[s1 * (H / 2) + fl]);
            float2 f2 = __half22float2(g_xw2h[s2 * (H / 2) + fl]);
            float2 f3 = __half22float2(g_xw2h[s3 * (H / 2) + fl]);
            ax += (f0.x + f1.x) + (f2.x + f3.x);
            ay += (f0.y + f1.y) + (f2.y + f3.y);
        }
        // 2 edges per iteration
        for (; i + 2 <= end; i += 2) {
            int s = __ldg(&g_esrc[i + sub]);
            float2 f = __half22float2(g_xw2h[s * (H / 2) + fl]);
            ax += f.x; ay += f.y;
        }
        // odd leftover: half-warp 0 only
        if (i < end && sub == 0) {
            int s = __ldg(&g_esrc[i]);
            float2 f = __half22float2(g_xw2h[s * (H / 2) + fl]);
            ax += f.x; ay += f.y;
        }
        // combine the two half-warps
        ax += __shfl_xor_sync(0xffffffffu, ax, 16);
        ay += __shfl_xor_sync(0xffffffffu, ay, 16);

        if (sub == 0) {
            float d  = (float)(deg > 0 ? deg : 1);
            float dn = rsqrtf(d);
            float2 o = make_float2(ax * dn + bx, ay * dn + by);
            reinterpret_cast<float2*>(out)[row * (H / 2) + fl] = o;
        }
    }
}

// ---------------- launch ----------------
extern "C" void kernel_launch(void* const* d_in, const int* in_sizes, int n_in,
                              void* d_out, int out_size) {
    const float* x    = (const float*)d_in[0];
    const int*   src  = (const int*)  d_in[1];
    const int*   dst  = (const int*)  d_in[2];
    const float* Wlin = (const float*)d_in[3];
    const float* blin = (const float*)d_in[4];
    const float* Wgc  = (const float*)d_in[5];
    const float* bgc  = (const float*)d_in[6];
    float* out = (float*)d_out;

    int n  = in_sizes[0] / DIN;
    int E  = in_sizes[1];
    int h1 = in_sizes[4];
    int nb = (n + CHUNK - 1) / CHUNK;

    k_init<<<256, 256>>>(Wlin, blin, Wgc, h1, n);     // launch 1
    k_deg<<<1024, 256>>>(src, dst, E);                // launch 2
    k_scan1<<<nb, CHUNK>>>(n, nb);                    // launch 3 (needs deg_in)

    static const size_t smemsz = (size_t)(TILE_R * DIN + DIN * H) * sizeof(float);
    cudaFuncSetAttribute(k_gemm, cudaFuncAttributeMaxDynamicSharedMemorySize, (int)smemsz);
    int gblk = (n + TILE_R - 1) / TILE_R;
    k_gemm<<<gblk, 256, smemsz>>>(x, n);              // launch 4  <-- profiled slot

    k_scan2<<<1, MAX_BLOCKS_SCAN>>>(nb);              // launch 5
    k_scan3<<<nb, CHUNK>>>(n);                        // launch 6
    k_scatter<<<2048, 256>>>(src, dst, E);            // launch 7
    k_agg<<<1184, 256>>>(out, bgc, n);                // launch 8
}

// round 8
// speedup vs baseline: 1.4142x; 1.1336x over previous
#include <cuda_runtime.h>
#include <cuda_fp16.h>

#define DIN 128
#define H   32
#define MAX_NODES 100000
#define MAX_EDGES 3200000
#define CHUNK 256
#define MAX_BLOCKS_SCAN 512
#define TILE_R 64    // rows per block in GEMM (48KB smem -> 4 blocks/SM)
#define WR 8         // rows per warp

// ---------------- scratch ----------------
__device__ float   g_Wf[DIN * H];
__device__ float   g_bf[H];
__device__ int     g_deg_out[MAX_NODES];
__device__ int     g_deg_in[MAX_NODES];
__device__ int     g_off[MAX_NODES];
__device__ int     g_cursor[MAX_NODES];
__device__ int     g_blocksum[MAX_BLOCKS_SCAN];
__device__ int     g_blockoff[MAX_BLOCKS_SCAN];
__device__ int     g_esrc[MAX_EDGES];
__device__ __half2 g_xw2h[MAX_NODES * (H / 2)];  // fp16 packed features, 64B/row

// ---------------- init: zero degrees + fuse weights ----------------
__global__ void k_init(const float* __restrict__ Wlin, const float* __restrict__ blin,
                       const float* __restrict__ Wgc, int h1, int n) {
    int idx = blockIdx.x * blockDim.x + threadIdx.x;
    int stride = gridDim.x * blockDim.x;
    for (int i = idx; i < n; i += stride) { g_deg_out[i] = 0; g_deg_in[i] = 0; }

    if (idx < DIN * H) {
        int i = idx / H, j = idx % H;
        float s = 0.f;
        for (int k = 0; k < h1; k++) s += Wlin[i * h1 + k] * Wgc[k * H + j];
        g_Wf[idx] = s;
    }
    if (idx < H) {
        float s = 0.f;
        for (int k = 0; k < h1; k++) s += blin[k] * Wgc[k * H + idx];
        g_bf[idx] = s;
    }
}

// ---------------- degree histograms ----------------
__global__ void __launch_bounds__(256) k_deg(const int* __restrict__ src,
                                             const int* __restrict__ dst, int E) {
    int i = blockIdx.x * blockDim.x + threadIdx.x;
    int stride = gridDim.x * blockDim.x;
    int E2 = E >> 1;
    const int2* s2 = reinterpret_cast<const int2*>(src);
    const int2* d2 = reinterpret_cast<const int2*>(dst);
    for (int j = i; j < E2; j += stride) {
        int2 s = __ldg(&s2[j]);
        int2 d = __ldg(&d2[j]);
        atomicAdd(&g_deg_out[s.x], 1);
        atomicAdd(&g_deg_out[s.y], 1);
        atomicAdd(&g_deg_in[d.x],  1);
        atomicAdd(&g_deg_in[d.y],  1);
    }
    if (i == 0 && (E & 1)) {
        atomicAdd(&g_deg_out[src[E - 1]], 1);
        atomicAdd(&g_deg_in[dst[E - 1]],  1);
    }
}

// ---------------- scan pass 1: per-chunk sums (shuffle reduce) ----------------
__global__ void k_scan1(int n, int nb) {
    __shared__ int ws[8];
    int t = threadIdx.x;
    int i = blockIdx.x * CHUNK + t;
    int v = (i < n) ? g_deg_in[i] : 0;
#pragma unroll
    for (int o = 16; o > 0; o >>= 1) v += __shfl_xor_sync(0xffffffffu, v, o);
    if ((t & 31) == 0) ws[t >> 5] = v;
    __syncthreads();
    if (t < 8) {
        int s = ws[t];
#pragma unroll
        for (int o = 4; o > 0; o >>= 1) s += __shfl_xor_sync(0xffu, s, o);
        if (t == 0) g_blocksum[blockIdx.x] = s;
    }
}

// ---------------- fused GEMM + out-degree norm (64-row tile, 4 blocks/SM) ----------------
__global__ void __launch_bounds__(256, 4) k_gemm(const float* __restrict__ x, int n) {
    extern __shared__ float smem[];
    float* sX = smem;                 // TILE_R*DIN (32KB)
    float* sW = smem + TILE_R * DIN;  // DIN*H (16KB)

    int tid = threadIdx.x;
    for (int t = tid; t < DIN * H; t += 256) sW[t] = g_Wf[t];

    int row0 = blockIdx.x * TILE_R;
    float4* sX4 = reinterpret_cast<float4*>(sX);
    const float4* xg = reinterpret_cast<const float4*>(x);
    int base4 = row0 * (DIN / 4);
    // 64*32 = 2048 float4, 256 threads -> 8 independent loads each (good MLP)
#pragma unroll
    for (int i = tid; i < TILE_R * (DIN / 4); i += 256) {
        int row = row0 + (i >> 5);
        sX4[i] = (row < n) ? __ldg(&xg[base4 + i]) : make_float4(0.f, 0.f, 0.f, 0.f);
    }
    __syncthreads();

    int w = tid >> 5, lane = tid & 31;
    float bias = g_bf[lane];
    int r0 = w * WR;

    float acc[WR];
#pragma unroll
    for (int r = 0; r < WR; r++) acc[r] = 0.f;

#pragma unroll 4
    for (int k4 = 0; k4 < DIN / 4; k4++) {
        float w0 = sW[(k4 * 4 + 0) * H + lane];
        float w1 = sW[(k4 * 4 + 1) * H + lane];
        float w2 = sW[(k4 * 4 + 2) * H + lane];
        float w3 = sW[(k4 * 4 + 3) * H + lane];
        // batch all 8 row-loads first to maximize LDS MLP
        float4 v[WR];
#pragma unroll
        for (int r = 0; r < WR; r++) v[r] = sX4[(r0 + r) * (DIN / 4) + k4];
#pragma unroll
        for (int r = 0; r < WR; r++)
            acc[r] += v[r].x * w0 + v[r].y * w1 + v[r].z * w2 + v[r].w * w3;
    }

#pragma unroll
    for (int r = 0; r < WR; r++) {
        int row = row0 + r0 + r;
        if (row < n) {
            float d = (float)g_deg_out[row];
            if (d < 1.f) d = 1.f;
            float val = (acc[r] + bias) * rsqrtf(d);
            float vo = __shfl_down_sync(0xffffffffu, val, 1);
            if ((lane & 1) == 0)
                g_xw2h[row * (H / 2) + (lane >> 1)] = __floats2half2_rn(val, vo);
        }
    }
}

// ---------------- scan pass 2 ----------------
__global__ void k_scan2(int nb) {
    __shared__ int s[MAX_BLOCKS_SCAN];
    int t = threadIdx.x;
    int v = (t < nb) ? g_blocksum[t] : 0;
    s[t] = v;
    __syncthreads();
    for (int off = 1; off < MAX_BLOCKS_SCAN; off <<= 1) {
        int add = (t >= off) ? s[t - off] : 0;
        __syncthreads();
        s[t] += add;
        __syncthreads();
    }
    if (t < nb) g_blockoff[t] = s[t] - v;
}

// ---------------- scan pass 3 ----------------
__global__ void k_scan3(int n) {
    __shared__ int s[CHUNK];
    int t = threadIdx.x;
    int i = blockIdx.x * CHUNK + t;
    int v = (i < n) ? g_deg_in[i] : 0;
    s[t] = v;
    __syncthreads();
    for (int off = 1; off < CHUNK; off <<= 1) {
        int add = (t >= off) ? s[t - off] : 0;
        __syncthreads();
        s[t] += add;
        __syncthreads();
    }
    if (i < n) {
        int off = g_blockoff[blockIdx.x] + s[t] - v;
        g_off[i]    = off;
        g_cursor[i] = off;
    }
}

// ---------------- counting-sort scatter (int2 unrolled) ----------------
__global__ void __launch_bounds__(256) k_scatter(const int* __restrict__ src,
                                                 const int* __restrict__ dst, int E) {
    int i = blockIdx.x * blockDim.x + threadIdx.x;
    int stride = gridDim.x * blockDim.x;
    int E2 = E >> 1;
    const int2* s2 = reinterpret_cast<const int2*>(src);
    const int2* d2 = reinterpret_cast<const int2*>(dst);
    for (int j = i; j < E2; j += stride) {
        int2 s = __ldg(&s2[j]);
        int2 d = __ldg(&d2[j]);
        int p0 = atomicAdd(&g_cursor[d.x], 1);
        int p1 = atomicAdd(&g_cursor[d.y], 1);
        g_esrc[p0] = s.x;
        g_esrc[p1] = s.y;
    }
    if (i == 0 && (E & 1)) {
        int p = atomicAdd(&g_cursor[dst[E - 1]], 1);
        g_esrc[p] = src[E - 1];
    }
}

// ---------------- gather-aggregate: half-warp per edge, MLP=8, fp16 rows ----------------
__global__ void __launch_bounds__(256) k_agg(float* __restrict__ out,
                                             const float* __restrict__ bgc, int n) {
    int warp   = (blockIdx.x * blockDim.x + threadIdx.x) >> 5;
    int lane   = threadIdx.x & 31;
    int nwarps = (gridDim.x * blockDim.x) >> 5;
    int sub    = lane >> 4;   // which edge-group of the pair
    int fl     = lane & 15;   // feature-pair index
    float bx = __ldg(&bgc[2 * fl]);
    float by = __ldg(&bgc[2 * fl + 1]);

    for (int row = warp; row < n; row += nwarps) {
        int start = g_off[row];
        int deg   = g_deg_in[row];
        int end   = start + deg;
        float ax = 0.f, ay = 0.f;
        int i = start;
        // 16 edges per warp-iteration (8 per half-warp) for MLP
        for (; i + 16 <= end; i += 16) {
            int base = i + sub * 8;
            int s0 = __ldg(&g_esrc[base + 0]);
            int s1 = __ldg(&g_esrc[base + 1]);
            int s2 = __ldg(&g_esrc[base + 2]);
            int s3 = __ldg(&g_esrc[base + 3]);
            int s4 = __ldg(&g_esrc[base + 4]);
            int s5 = __ldg(&g_esrc[base + 5]);
            int s6 = __ldg(&g_esrc[base + 6]);
            int s7 = __ldg(&g_esrc[base + 7]);
            float2 f0 = __half22float2(g_xw2h[s0 * (H / 2) + fl]);
            float2 f1 = __half22float2(g_xw2h[s1 * (H / 2) + fl]);
            float2 f2 = __half22float2(g_xw2h[s2 * (H / 2) + fl]);
            float2 f3 = __half22float2(g_xw2h[s3 * (H / 2) + fl]);
            float2 f4 = __half22float2(g_xw2h[s4 * (H / 2) + fl]);
            float2 f5 = __half22float2(g_xw2h[s5 * (H / 2) + fl]);
            float2 f6 = __half22float2(g_xw2h[s6 * (H / 2) + fl]);
            float2 f7 = __half22float2(g_xw2h[s7 * (H / 2) + fl]);
            ax += ((f0.x + f1.x) + (f2.x + f3.x)) + ((f4.x + f5.x) + (f6.x + f7.x));
            ay += ((f0.y + f1.y) + (f2.y + f3.y)) + ((f4.y + f5.y) + (f6.y + f7.y));
        }
        // 2 edges per iteration
        for (; i + 2 <= end; i += 2) {
            int s = __ldg(&g_esrc[i + sub]);
            float2 f = __half22float2(g_xw2h[s * (H / 2) + fl]);
            ax += f.x; ay += f.y;
        }
        // odd leftover: half-warp 0 only
        if (i < end && sub == 0) {
            int s = __ldg(&g_esrc[i]);
            float2 f = __half22float2(g_xw2h[s * (H / 2) + fl]);
            ax += f.x; ay += f.y;
        }
        // combine the two half-warps
        ax += __shfl_xor_sync(0xffffffffu, ax, 16);
        ay += __shfl_xor_sync(0xffffffffu, ay, 16);

        if (sub == 0) {
            float d  = (float)(deg > 0 ? deg : 1);
            float dn = rsqrtf(d);
            float2 o = make_float2(ax * dn + bx, ay * dn + by);
            reinterpret_cast<float2*>(out)[row * (H / 2) + fl] = o;
        }
    }
}

// ---------------- launch ----------------
extern "C" void kernel_launch(void* const* d_in, const int* in_sizes, int n_in,
                              void* d_out, int out_size) {
    const float* x    = (const float*)d_in[0];
    const int*   src  = (const int*)  d_in[1];
    const int*   dst  = (const int*)  d_in[2];
    const float* Wlin = (const float*)d_in[3];
    const float* blin = (const float*)d_in[4];
    const float* Wgc  = (const float*)d_in[5];
    const float* bgc  = (const float*)d_in[6];
    float* out = (float*)d_out;

    int n  = in_sizes[0] / DIN;
    int E  = in_sizes[1];
    int h1 = in_sizes[4];
    int nb = (n + CHUNK - 1) / CHUNK;

    k_init<<<256, 256>>>(Wlin, blin, Wgc, h1, n);     // 1
    k_deg<<<1024, 256>>>(src, dst, E);                // 2
    k_scan1<<<nb, CHUNK>>>(n, nb);                    // 3

    static const size_t smemsz = (size_t)(TILE_R * DIN + DIN * H) * sizeof(float);  // 48KB
    cudaFuncSetAttribute(k_gemm, cudaFuncAttributeMaxDynamicSharedMemorySize, (int)smemsz);
    int gblk = (n + TILE_R - 1) / TILE_R;
    k_gemm<<<gblk, 256, smemsz>>>(x, n);              // 4  <-- profiled slot

    k_scan2<<<1, MAX_BLOCKS_SCAN>>>(nb);              // 5
    k_scan3<<<nb, CHUNK>>>(n);                        // 6
    k_scatter<<<2048, 256>>>(src, dst, E);            // 7
    k_agg<<<1184, 256>>>(out, bgc, n);                // 8
}

// round 9
// speedup vs baseline: 1.4651x; 1.0360x over previous
#include <cuda_runtime.h>
#include <cuda_fp16.h>

#define DIN 128
#define H   32
#define MAX_NODES 100000
#define MAX_EDGES 3200000
#define CHUNK 256
#define MAX_BLOCKS_SCAN 512
#define GP4 34   // x-tile pitch in float4 units (136 floats)

// ---------------- scratch ----------------
__device__ float   g_Wf[DIN * H];
__device__ float   g_bf[H];
__device__ int     g_deg_out[MAX_NODES];
__device__ int     g_deg_in[MAX_NODES];
__device__ int     g_off[MAX_NODES];
__device__ int     g_cursor[MAX_NODES];
__device__ int     g_blocksum[MAX_BLOCKS_SCAN];
__device__ int     g_blockoff[MAX_BLOCKS_SCAN];
__device__ int     g_esrc[MAX_EDGES];
__device__ __half2 g_xw2h[MAX_NODES * (H / 2)];  // fp16 packed features, 64B/row

// ---------------- init: zero degrees + fuse weights ----------------
__global__ void k_init(const float* __restrict__ Wlin, const float* __restrict__ blin,
                       const float* __restrict__ Wgc, int h1, int n) {
    int idx = blockIdx.x * blockDim.x + threadIdx.x;
    int stride = gridDim.x * blockDim.x;
    for (int i = idx; i < n; i += stride) { g_deg_out[i] = 0; g_deg_in[i] = 0; }

    if (idx < DIN * H) {
        int i = idx / H, j = idx % H;
        float s = 0.f;
        for (int k = 0; k < h1; k++) s += Wlin[i * h1 + k] * Wgc[k * H + j];
        g_Wf[idx] = s;
    }
    if (idx < H) {
        float s = 0.f;
        for (int k = 0; k < h1; k++) s += blin[k] * Wgc[k * H + idx];
        g_bf[idx] = s;
    }
}

// ---------------- degree histograms ----------------
__global__ void __launch_bounds__(256) k_deg(const int* __restrict__ src,
                                             const int* __restrict__ dst, int E) {
    int i = blockIdx.x * blockDim.x + threadIdx.x;
    int stride = gridDim.x * blockDim.x;
    int E2 = E >> 1;
    const int2* s2 = reinterpret_cast<const int2*>(src);
    const int2* d2 = reinterpret_cast<const int2*>(dst);
    for (int j = i; j < E2; j += stride) {
        int2 s = __ldg(&s2[j]);
        int2 d = __ldg(&d2[j]);
        atomicAdd(&g_deg_out[s.x], 1);
        atomicAdd(&g_deg_out[s.y], 1);
        atomicAdd(&g_deg_in[d.x],  1);
        atomicAdd(&g_deg_in[d.y],  1);
    }
    if (i == 0 && (E & 1)) {
        atomicAdd(&g_deg_out[src[E - 1]], 1);
        atomicAdd(&g_deg_in[dst[E - 1]],  1);
    }
}

// ---------------- scan pass 1: per-chunk sums (shuffle reduce) ----------------
__global__ void k_scan1(int n, int nb) {
    __shared__ int ws[8];
    int t = threadIdx.x;
    int i = blockIdx.x * CHUNK + t;
    int v = (i < n) ? g_deg_in[i] : 0;
#pragma unroll
    for (int o = 16; o > 0; o >>= 1) v += __shfl_xor_sync(0xffffffffu, v, o);
    if ((t & 31) == 0) ws[t >> 5] = v;
    __syncthreads();
    if (t < 8) {
        int s = ws[t];
#pragma unroll
        for (int o = 4; o > 0; o >>= 1) s += __shfl_xor_sync(0xffu, s, o);
        if (t == 0) g_blocksum[blockIdx.x] = s;
    }
}

// ---------------- fused GEMM: register micro-tiled 8x4, 128 threads/block ----------------
// Block tile: 128 rows x 32 cols. tx = tid%8 -> cols 4tx..4tx+3; ty = tid/8 -> rows 8ty..8ty+7.
// x tile staged row-major, float4-swizzled: chunk c = k4 ^ ((row>>3)&7) -> conflict-free
// STS.128 on stage and LDS.128 on a-frag loads (4 distinct addrs per warp, distinct bank quads).
__global__ void __launch_bounds__(128, 2) k_gemm(const float* __restrict__ x, int n) {
    extern __shared__ float smem[];
    float4* sX4 = reinterpret_cast<float4*>(smem);     // 128 rows * GP4 float4
    float*  sW  = smem + 128 * (GP4 * 4);              // DIN*H floats
    int tid = threadIdx.x;

    for (int t = tid; t < DIN * H; t += 128) sW[t] = g_Wf[t];

    int row0 = blockIdx.x * 128;
    const float4* xg = reinterpret_cast<const float4*>(x);
#pragma unroll 8
    for (int it = 0; it < 32; it++) {
        int i = it * 128 + tid;
        int row = i >> 5;        // 0..127 (32 float4 per row)
        int k4  = i & 31;
        float4 v = make_float4(0.f, 0.f, 0.f, 0.f);
        if (row0 + row < n) v = __ldg(&xg[(size_t)(row0 + row) * 32 + k4]);
        sX4[row * GP4 + (k4 ^ ((row >> 3) & 7))] = v;
    }
    __syncthreads();

    int tx = tid & 7;
    int ty = tid >> 3;          // 0..15
    int sw = ty & 7;            // swizzle key for this thread's rows ((8ty+r)>>3 == ty)
    const float4* sW4 = reinterpret_cast<const float4*>(sW);

    float acc[8][4];
#pragma unroll
    for (int r = 0; r < 8; r++)
#pragma unroll
        for (int c = 0; c < 4; c++) acc[r][c] = 0.f;

#pragma unroll 2
    for (int k4 = 0; k4 < 32; k4++) {
        int c = k4 ^ sw;
        float4 a[8];
#pragma unroll
        for (int r = 0; r < 8; r++) a[r] = sX4[(8 * ty + r) * GP4 + c];
        float4 b0 = sW4[(k4 * 4 + 0) * 8 + tx];
        float4 b1 = sW4[(k4 * 4 + 1) * 8 + tx];
        float4 b2 = sW4[(k4 * 4 + 2) * 8 + tx];
        float4 b3 = sW4[(k4 * 4 + 3) * 8 + tx];
#pragma unroll
        for (int r = 0; r < 8; r++) {
            acc[r][0] += a[r].x * b0.x + a[r].y * b1.x + a[r].z * b2.x + a[r].w * b3.x;
            acc[r][1] += a[r].x * b0.y + a[r].y * b1.y + a[r].z * b2.y + a[r].w * b3.y;
            acc[r][2] += a[r].x * b0.z + a[r].y * b1.z + a[r].z * b2.z + a[r].w * b3.z;
            acc[r][3] += a[r].x * b0.w + a[r].y * b1.w + a[r].z * b2.w + a[r].w * b3.w;
        }
    }

    float bf0 = g_bf[4 * tx + 0];
    float bf1 = g_bf[4 * tx + 1];
    float bf2 = g_bf[4 * tx + 2];
    float bf3 = g_bf[4 * tx + 3];
#pragma unroll
    for (int r = 0; r < 8; r++) {
        int row = row0 + 8 * ty + r;
        if (row < n) {
            float dd = (float)g_deg_out[row];
            if (dd < 1.f) dd = 1.f;
            float s = rsqrtf(dd);
            __half2 h0 = __floats2half2_rn((acc[r][0] + bf0) * s, (acc[r][1] + bf1) * s);
            __half2 h1 = __floats2half2_rn((acc[r][2] + bf2) * s, (acc[r][3] + bf3) * s);
            __half2* dp = &g_xw2h[row * (H / 2) + 2 * tx];
            dp[0] = h0;
            dp[1] = h1;
        }
    }
}

// ---------------- scan pass 2 ----------------
__global__ void k_scan2(int nb) {
    __shared__ int s[MAX_BLOCKS_SCAN];
    int t = threadIdx.x;
    int v = (t < nb) ? g_blocksum[t] : 0;
    s[t] = v;
    __syncthreads();
    for (int off = 1; off < MAX_BLOCKS_SCAN; off <<= 1) {
        int add = (t >= off) ? s[t - off] : 0;
        __syncthreads();
        s[t] += add;
        __syncthreads();
    }
    if (t < nb) g_blockoff[t] = s[t] - v;
}

// ---------------- scan pass 3 ----------------
__global__ void k_scan3(int n) {
    __shared__ int s[CHUNK];
    int t = threadIdx.x;
    int i = blockIdx.x * CHUNK + t;
    int v = (i < n) ? g_deg_in[i] : 0;
    s[t] = v;
    __syncthreads();
    for (int off = 1; off < CHUNK; off <<= 1) {
        int add = (t >= off) ? s[t - off] : 0;
        __syncthreads();
        s[t] += add;
        __syncthreads();
    }
    if (i < n) {
        int off = g_blockoff[blockIdx.x] + s[t] - v;
        g_off[i]    = off;
        g_cursor[i] = off;
    }
}

// ---------------- counting-sort scatter (int2 unrolled) ----------------
__global__ void __launch_bounds__(256) k_scatter(const int* __restrict__ src,
                                                 const int* __restrict__ dst, int E) {
    int i = blockIdx.x * blockDim.x + threadIdx.x;
    int stride = gridDim.x * blockDim.x;
    int E2 = E >> 1;
    const int2* s2 = reinterpret_cast<const int2*>(src);
    const int2* d2 = reinterpret_cast<const int2*>(dst);
    for (int j = i; j < E2; j += stride) {
        int2 s = __ldg(&s2[j]);
        int2 d = __ldg(&d2[j]);
        int p0 = atomicAdd(&g_cursor[d.x], 1);
        int p1 = atomicAdd(&g_cursor[d.y], 1);
        g_esrc[p0] = s.x;
        g_esrc[p1] = s.y;
    }
    if (i == 0 && (E & 1)) {
        int p = atomicAdd(&g_cursor[dst[E - 1]], 1);
        g_esrc[p] = src[E - 1];
    }
}

// ---------------- gather-aggregate: half-warp per edge, MLP=8, fp16 rows ----------------
__global__ void __launch_bounds__(256) k_agg(float* __restrict__ out,
                                             const float* __restrict__ bgc, int n) {
    int warp   = (blockIdx.x * blockDim.x + threadIdx.x) >> 5;
    int lane   = threadIdx.x & 31;
    int nwarps = (gridDim.x * blockDim.x) >> 5;
    int sub    = lane >> 4;
    int fl     = lane & 15;
    float bx = __ldg(&bgc[2 * fl]);
    float by = __ldg(&bgc[2 * fl + 1]);

    for (int row = warp; row < n; row += nwarps) {
        int start = g_off[row];
        int deg   = g_deg_in[row];
        int end   = start + deg;
        float ax = 0.f, ay = 0.f;
        int i = start;
        for (; i + 16 <= end; i += 16) {
            int base = i + sub * 8;
            int s0 = __ldg(&g_esrc[base + 0]);
            int s1 = __ldg(&g_esrc[base + 1]);
            int s2 = __ldg(&g_esrc[base + 2]);
            int s3 = __ldg(&g_esrc[base + 3]);
            int s4 = __ldg(&g_esrc[base + 4]);
            int s5 = __ldg(&g_esrc[base + 5]);
            int s6 = __ldg(&g_esrc[base + 6]);
            int s7 = __ldg(&g_esrc[base + 7]);
            float2 f0 = __half22float2(g_xw2h[s0 * (H / 2) + fl]);
            float2 f1 = __half22float2(g_xw2h[s1 * (H / 2) + fl]);
            float2 f2 = __half22float2(g_xw2h[s2 * (H / 2) + fl]);
            float2 f3 = __half22float2(g_xw2h[s3 * (H / 2) + fl]);
            float2 f4 = __half22float2(g_xw2h[s4 * (H / 2) + fl]);
            float2 f5 = __half22float2(g_xw2h[s5 * (H / 2) + fl]);
            float2 f6 = __half22float2(g_xw2h[s6 * (H / 2) + fl]);
            float2 f7 = __half22float2(g_xw2h[s7 * (H / 2) + fl]);
            ax += ((f0.x + f1.x) + (f2.x + f3.x)) + ((f4.x + f5.x) + (f6.x + f7.x));
            ay += ((f0.y + f1.y) + (f2.y + f3.y)) + ((f4.y + f5.y) + (f6.y + f7.y));
        }
        for (; i + 2 <= end; i += 2) {
            int s = __ldg(&g_esrc[i + sub]);
            float2 f = __half22float2(g_xw2h[s * (H / 2) + fl]);
            ax += f.x; ay += f.y;
        }
        if (i < end && sub == 0) {
            int s = __ldg(&g_esrc[i]);
            float2 f = __half22float2(g_xw2h[s * (H / 2) + fl]);
            ax += f.x; ay += f.y;
        }
        ax += __shfl_xor_sync(0xffffffffu, ax, 16);
        ay += __shfl_xor_sync(0xffffffffu, ay, 16);

        if (sub == 0) {
            float d  = (float)(deg > 0 ? deg : 1);
            float dn = rsqrtf(d);
            float2 o = make_float2(ax * dn + bx, ay * dn + by);
            reinterpret_cast<float2*>(out)[row * (H / 2) + fl] = o;
        }
    }
}

// ---------------- launch ----------------
extern "C" void kernel_launch(void* const* d_in, const int* in_sizes, int n_in,
                              void* d_out, int out_size) {
    const float* x    = (const float*)d_in[0];
    const int*   src  = (const int*)  d_in[1];
    const int*   dst  = (const int*)  d_in[2];
    const float* Wlin = (const float*)d_in[3];
    const float* blin = (const float*)d_in[4];
    const float* Wgc  = (const float*)d_in[5];
    const float* bgc  = (const float*)d_in[6];
    float* out = (float*)d_out;

    int n  = in_sizes[0] / DIN;
    int E  = in_sizes[1];
    int h1 = in_sizes[4];
    int nb = (n + CHUNK - 1) / CHUNK;

    k_init<<<256, 256>>>(Wlin, blin, Wgc, h1, n);     // 1
    k_deg<<<1024, 256>>>(src, dst, E);                // 2
    k_scan1<<<nb, CHUNK>>>(n, nb);                    // 3

    static const size_t smemsz = (size_t)(128 * GP4 * 4 + DIN * H) * sizeof(float);  // 86016
    cudaFuncSetAttribute(k_gemm, cudaFuncAttributeMaxDynamicSharedMemorySize, (int)smemsz);
    int gblk = (n + 127) / 128;
    k_gemm<<<gblk, 128, smemsz>>>(x, n);              // 4  <-- profiled slot

    k_scan2<<<1, MAX_BLOCKS_SCAN>>>(nb);              // 5
    k_scan3<<<nb, CHUNK>>>(n);                        // 6
    k_scatter<<<2048, 256>>>(src, dst, E);            // 7
    k_agg<<<1184, 256>>>(out, bgc, n);                // 8
}

// round 10
// speedup vs baseline: 1.4780x; 1.0088x over previous
#include <cuda_runtime.h>
#include <cuda_fp16.h>

#define DIN 128
#define H   32
#define MAX_NODES 100000
#define MAX_EDGES 3200000
#define CHUNK 256
#define MAX_BLOCKS_SCAN 512
#define XP4 17   // x half-tile pitch in float4 units (padding kills bank conflicts)

// ---------------- scratch ----------------
__device__ float   g_Wf[DIN * H];
__device__ float   g_bf[H];
__device__ int     g_deg_out[MAX_NODES];
__device__ int     g_deg_in[MAX_NODES];
__device__ int     g_off[MAX_NODES];
__device__ int     g_cursor[MAX_NODES];
__device__ int     g_blocksum[MAX_BLOCKS_SCAN];
__device__ int     g_blockoff[MAX_BLOCKS_SCAN];
__device__ int     g_esrc[MAX_EDGES];
__device__ __half2 g_xw2h[MAX_NODES * (H / 2)];  // fp16 packed features, 64B/row

// ---------------- init: zero degrees + fuse weights ----------------
__global__ void k_init(const float* __restrict__ Wlin, const float* __restrict__ blin,
                       const float* __restrict__ Wgc, int h1, int n) {
    int idx = blockIdx.x * blockDim.x + threadIdx.x;
    int stride = gridDim.x * blockDim.x;
    for (int i = idx; i < n; i += stride) { g_deg_out[i] = 0; g_deg_in[i] = 0; }

    if (idx < DIN * H) {
        int i = idx / H, j = idx % H;
        float s = 0.f;
        for (int k = 0; k < h1; k++) s += Wlin[i * h1 + k] * Wgc[k * H + j];
        g_Wf[idx] = s;
    }
    if (idx < H) {
        float s = 0.f;
        for (int k = 0; k < h1; k++) s += blin[k] * Wgc[k * H + idx];
        g_bf[idx] = s;
    }
}

// ---------------- degree histograms ----------------
__global__ void __launch_bounds__(256) k_deg(const int* __restrict__ src,
                                             const int* __restrict__ dst, int E) {
    int i = blockIdx.x * blockDim.x + threadIdx.x;
    int stride = gridDim.x * blockDim.x;
    int E2 = E >> 1;
    const int2* s2 = reinterpret_cast<const int2*>(src);
    const int2* d2 = reinterpret_cast<const int2*>(dst);
    for (int j = i; j < E2; j += stride) {
        int2 s = __ldg(&s2[j]);
        int2 d = __ldg(&d2[j]);
        atomicAdd(&g_deg_out[s.x], 1);
        atomicAdd(&g_deg_out[s.y], 1);
        atomicAdd(&g_deg_in[d.x],  1);
        atomicAdd(&g_deg_in[d.y],  1);
    }
    if (i == 0 && (E & 1)) {
        atomicAdd(&g_deg_out[src[E - 1]], 1);
        atomicAdd(&g_deg_in[dst[E - 1]],  1);
    }
}

// ---------------- scan pass 1: per-chunk sums (shuffle reduce) ----------------
__global__ void k_scan1(int n, int nb) {
    __shared__ int ws[8];
    int t = threadIdx.x;
    int i = blockIdx.x * CHUNK + t;
    int v = (i < n) ? g_deg_in[i] : 0;
#pragma unroll
    for (int o = 16; o > 0; o >>= 1) v += __shfl_xor_sync(0xffffffffu, v, o);
    if ((t & 31) == 0) ws[t >> 5] = v;
    __syncthreads();
    if (t < 8) {
        int s = ws[t];
#pragma unroll
        for (int o = 4; o > 0; o >>= 1) s += __shfl_xor_sync(0xffu, s, o);
        if (t == 0) g_blocksum[blockIdx.x] = s;
    }
}

// ---------------- fused GEMM: 8x4 micro-tile, k-split halves, 4 blocks/SM ----------------
// Block tile 128 rows x 32 cols; thread (tx=tid&7, ty=tid>>3) owns rows 8ty..8ty+7,
// cols 4tx..4tx+3. x staged one K-half (64 cols) at a time: 34.8KB + 16KB W = 51KB.
__global__ void __launch_bounds__(128, 4) k_gemm(const float* __restrict__ x, int n) {
    extern __shared__ float smem[];
    float4* sX4 = reinterpret_cast<float4*>(smem);     // 128 * XP4 float4 (34.8KB)
    float*  sW  = smem + 128 * XP4 * 4;                // DIN*H floats (16KB)
    int tid = threadIdx.x;

    for (int t = tid; t < DIN * H; t += 128) sW[t] = g_Wf[t];

    int row0 = blockIdx.x * 128;
    const float4* xg = reinterpret_cast<const float4*>(x);
    int tx = tid & 7;
    int ty = tid >> 3;          // 0..15
    const float4* sW4 = reinterpret_cast<const float4*>(sW);

    float acc[8][4];
#pragma unroll
    for (int r = 0; r < 8; r++)
#pragma unroll
        for (int c = 0; c < 4; c++) acc[r][c] = 0.f;

    for (int h = 0; h < 2; h++) {
        __syncthreads();   // first iter: W ready; second iter: buffer drained
        // stage K-half: 128 rows x 16 float4, coalesced (16 lanes/row)
#pragma unroll
        for (int it = 0; it < 16; it++) {
            int i = it * 128 + tid;
            int row = i >> 4;
            int k4  = i & 15;
            float4 v = make_float4(0.f, 0.f, 0.f, 0.f);
            if (row0 + row < n) v = __ldg(&xg[(size_t)(row0 + row) * 32 + h * 16 + k4]);
            sX4[row * XP4 + k4] = v;
        }
        __syncthreads();

#pragma unroll 4
        for (int k4 = 0; k4 < 16; k4++) {
            int kg = h * 16 + k4;
            float4 a[8];
#pragma unroll
            for (int r = 0; r < 8; r++) a[r] = sX4[(8 * ty + r) * XP4 + k4];
            float4 b0 = sW4[(kg * 4 + 0) * 8 + tx];
            float4 b1 = sW4[(kg * 4 + 1) * 8 + tx];
            float4 b2 = sW4[(kg * 4 + 2) * 8 + tx];
            float4 b3 = sW4[(kg * 4 + 3) * 8 + tx];
#pragma unroll
            for (int r = 0; r < 8; r++) {
                acc[r][0] += a[r].x * b0.x + a[r].y * b1.x + a[r].z * b2.x + a[r].w * b3.x;
                acc[r][1] += a[r].x * b0.y + a[r].y * b1.y + a[r].z * b2.y + a[r].w * b3.y;
                acc[r][2] += a[r].x * b0.z + a[r].y * b1.z + a[r].z * b2.z + a[r].w * b3.z;
                acc[r][3] += a[r].x * b0.w + a[r].y * b1.w + a[r].z * b2.w + a[r].w * b3.w;
            }
        }
    }

    float bf0 = g_bf[4 * tx + 0];
    float bf1 = g_bf[4 * tx + 1];
    float bf2 = g_bf[4 * tx + 2];
    float bf3 = g_bf[4 * tx + 3];
#pragma unroll
    for (int r = 0; r < 8; r++) {
        int row = row0 + 8 * ty + r;
        if (row < n) {
            float dd = (float)g_deg_out[row];
            if (dd < 1.f) dd = 1.f;
            float s = rsqrtf(dd);
            __half2 h0 = __floats2half2_rn((acc[r][0] + bf0) * s, (acc[r][1] + bf1) * s);
            __half2 h1 = __floats2half2_rn((acc[r][2] + bf2) * s, (acc[r][3] + bf3) * s);
            __half2* dp = &g_xw2h[row * (H / 2) + 2 * tx];
            dp[0] = h0;
            dp[1] = h1;
        }
    }
}

// ---------------- scan pass 2 ----------------
__global__ void k_scan2(int nb) {
    __shared__ int s[MAX_BLOCKS_SCAN];
    int t = threadIdx.x;
    int v = (t < nb) ? g_blocksum[t] : 0;
    s[t] = v;
    __syncthreads();
    for (int off = 1; off < MAX_BLOCKS_SCAN; off <<= 1) {
        int add = (t >= off) ? s[t - off] : 0;
        __syncthreads();
        s[t] += add;
        __syncthreads();
    }
    if (t < nb) g_blockoff[t] = s[t] - v;
}

// ---------------- scan pass 3 ----------------
__global__ void k_scan3(int n) {
    __shared__ int s[CHUNK];
    int t = threadIdx.x;
    int i = blockIdx.x * CHUNK + t;
    int v = (i < n) ? g_deg_in[i] : 0;
    s[t] = v;
    __syncthreads();
    for (int off = 1; off < CHUNK; off <<= 1) {
        int add = (t >= off) ? s[t - off] : 0;
        __syncthreads();
        s[t] += add;
        __syncthreads();
    }
    if (i < n) {
        int off = g_blockoff[blockIdx.x] + s[t] - v;
        g_off[i]    = off;
        g_cursor[i] = off;
    }
}

// ---------------- counting-sort scatter (int2 unrolled) ----------------
__global__ void __launch_bounds__(256) k_scatter(const int* __restrict__ src,
                                                 const int* __restrict__ dst, int E) {
    int i = blockIdx.x * blockDim.x + threadIdx.x;
    int stride = gridDim.x * blockDim.x;
    int E2 = E >> 1;
    const int2* s2 = reinterpret_cast<const int2*>(src);
    const int2* d2 = reinterpret_cast<const int2*>(dst);
    for (int j = i; j < E2; j += stride) {
        int2 s = __ldg(&s2[j]);
        int2 d = __ldg(&d2[j]);
        int p0 = atomicAdd(&g_cursor[d.x], 1);
        int p1 = atomicAdd(&g_cursor[d.y], 1);
        g_esrc[p0] = s.x;
        g_esrc[p1] = s.y;
    }
    if (i == 0 && (E & 1)) {
        int p = atomicAdd(&g_cursor[dst[E - 1]], 1);
        g_esrc[p] = src[E - 1];
    }
}

// ---------------- gather-aggregate: half-warp per edge, MLP=8, fp16 rows ----------------
__global__ void __launch_bounds__(256) k_agg(float* __restrict__ out,
                                             const float* __restrict__ bgc, int n) {
    int warp   = (blockIdx.x * blockDim.x + threadIdx.x) >> 5;
    int lane   = threadIdx.x & 31;
    int nwarps = (gridDim.x * blockDim.x) >> 5;
    int sub    = lane >> 4;
    int fl     = lane & 15;
    float bx = __ldg(&bgc[2 * fl]);
    float by = __ldg(&bgc[2 * fl + 1]);

    for (int row = warp; row < n; row += nwarps) {
        int start = g_off[row];
        int deg   = g_deg_in[row];
        int end   = start + deg;
        float ax = 0.f, ay = 0.f;
        int i = start;
        for (; i + 16 <= end; i += 16) {
            int base = i + sub * 8;
            int s0 = __ldg(&g_esrc[base + 0]);
            int s1 = __ldg(&g_esrc[base + 1]);
            int s2 = __ldg(&g_esrc[base + 2]);
            int s3 = __ldg(&g_esrc[base + 3]);
            int s4 = __ldg(&g_esrc[base + 4]);
            int s5 = __ldg(&g_esrc[base + 5]);
            int s6 = __ldg(&g_esrc[base + 6]);
            int s7 = __ldg(&g_esrc[base + 7]);
            float2 f0 = __half22float2(g_xw2h[s0 * (H / 2) + fl]);
            float2 f1 = __half22float2(g_xw2h[s1 * (H / 2) + fl]);
            float2 f2 = __half22float2(g_xw2h[s2 * (H / 2) + fl]);
            float2 f3 = __half22float2(g_xw2h[s3 * (H / 2) + fl]);
            float2 f4 = __half22float2(g_xw2h[s4 * (H / 2) + fl]);
            float2 f5 = __half22float2(g_xw2h[s5 * (H / 2) + fl]);
            float2 f6 = __half22float2(g_xw2h[s6 * (H / 2) + fl]);
            float2 f7 = __half22float2(g_xw2h[s7 * (H / 2) + fl]);
            ax += ((f0.x + f1.x) + (f2.x + f3.x)) + ((f4.x + f5.x) + (f6.x + f7.x));
            ay += ((f0.y + f1.y) + (f2.y + f3.y)) + ((f4.y + f5.y) + (f6.y + f7.y));
        }
        for (; i + 2 <= end; i += 2) {
            int s = __ldg(&g_esrc[i + sub]);
            float2 f = __half22float2(g_xw2h[s * (H / 2) + fl]);
            ax += f.x; ay += f.y;
        }
        if (i < end && sub == 0) {
            int s = __ldg(&g_esrc[i]);
            float2 f = __half22float2(g_xw2h[s * (H / 2) + fl]);
            ax += f.x; ay += f.y;
        }
        ax += __shfl_xor_sync(0xffffffffu, ax, 16);
        ay += __shfl_xor_sync(0xffffffffu, ay, 16);

        if (sub == 0) {
            float d  = (float)(deg > 0 ? deg : 1);
            float dn = rsqrtf(d);
            float2 o = make_float2(ax * dn + bx, ay * dn + by);
            reinterpret_cast<float2*>(out)[row * (H / 2) + fl] = o;
        }
    }
}

// ---------------- launch ----------------
extern "C" void kernel_launch(void* const* d_in, const int* in_sizes, int n_in,
                              void* d_out, int out_size) {
    const float* x    = (const float*)d_in[0];
    const int*   src  = (const int*)  d_in[1];
    const int*   dst  = (const int*)  d_in[2];
    const float* Wlin = (const float*)d_in[3];
    const float* blin = (const float*)d_in[4];
    const float* Wgc  = (const float*)d_in[5];
    const float* bgc  = (const float*)d_in[6];
    float* out = (float*)d_out;

    int n  = in_sizes[0] / DIN;
    int E  = in_sizes[1];
    int h1 = in_sizes[4];
    int nb = (n + CHUNK - 1) / CHUNK;

    k_init<<<256, 256>>>(Wlin, blin, Wgc, h1, n);     // 1
    k_deg<<<1024, 256>>>(src, dst, E);                // 2
    k_scan1<<<nb, CHUNK>>>(n, nb);                    // 3

    static const size_t smemsz = (size_t)(128 * XP4 * 4 + DIN * H) * sizeof(float);  // 51200
    cudaFuncSetAttribute(k_gemm, cudaFuncAttributeMaxDynamicSharedMemorySize, (int)smemsz);
    int gblk = (n + 127) / 128;
    k_gemm<<<gblk, 128, smemsz>>>(x, n);              // 4  <-- profiled slot

    k_scan2<<<1, MAX_BLOCKS_SCAN>>>(nb);              // 5
    k_scan3<<<nb, CHUNK>>>(n);                        // 6
    k_scatter<<<2048, 256>>>(src, dst, E);            // 7
    k_agg<<<2048, 256>>>(out, bgc, n);                // 8
}